// round 1
// baseline (speedup 1.0000x reference)
#include <cuda_runtime.h>

#define BB   16
#define NN   512
#define DIN  256
#define DD   64
#define EE   32
#define MAXDIST 50

// -------- scratch (no allocations allowed) --------
__device__ float g_q[BB*NN*DD];
__device__ float g_k[BB*NN*DD];
__device__ float g_v[BB*NN*DD];
__device__ float g_rel[MAXDIST+1];

// ============================================================
// Kernel 0: 51-entry relational-bias table.
// rel[d] = sigmoid( relu(Eemb[d] @ Wr1 + br1) @ Wr2 )
// ============================================================
__global__ void rel_table_kernel(const float* __restrict__ Eemb,
                                 const float* __restrict__ Wr1,
                                 const float* __restrict__ br1,
                                 const float* __restrict__ Wr2) {
    int d = threadIdx.x;
    if (d > MAXDIST) return;
    float e[EE];
#pragma unroll
    for (int c = 0; c < EE; c++) e[c] = Eemb[d*EE + c];
    float w = 0.f;
#pragma unroll
    for (int j = 0; j < 16; j++) {
        float h = br1[j];
#pragma unroll
        for (int c = 0; c < EE; c++) h = fmaf(e[c], Wr1[c*16 + j], h);
        h = fmaxf(h, 0.f);
        w = fmaf(h, Wr2[j], w);
    }
    g_rel[d] = 1.f / (1.f + __expf(-w));
}

// ============================================================
// Kernel 1: xp = x@Wp+bp ; q,k,v = xp@W{q,k,v}+b  (fused)
// One CTA = 64 rows. 256 threads, 16x16 thread grid, 4x4 register tiles.
// ============================================================
__global__ __launch_bounds__(256) void qkv_kernel(
    const float* __restrict__ x,
    const float* __restrict__ Wp, const float* __restrict__ bp,
    const float* __restrict__ Wq, const float* __restrict__ bq,
    const float* __restrict__ Wk, const float* __restrict__ bk,
    const float* __restrict__ Wv, const float* __restrict__ bv) {
    __shared__ float bufA[64*68];   // xT chunk, later xpT
    __shared__ float bufB[64*68];   // weight chunk
    const int tid = threadIdx.x;
    const int ty = tid >> 4, tx = tid & 15;
    const int row0 = blockIdx.x * 64;

    float acc[4][4];
#pragma unroll
    for (int r = 0; r < 4; r++)
#pragma unroll
        for (int c = 0; c < 4; c++) acc[r][c] = 0.f;

    for (int kc = 0; kc < 4; kc++) {
        for (int idx = tid; idx < 4096; idx += 256) {
            int i = idx >> 6, kk = idx & 63;
            bufA[kk*68 + i] = x[(row0 + i)*DIN + kc*64 + kk];       // transposed
        }
        for (int idx = tid; idx < 4096; idx += 256) {
            int kk = idx >> 6, j = idx & 63;
            bufB[kk*68 + j] = Wp[(kc*64 + kk)*DD + j];
        }
        __syncthreads();
#pragma unroll 8
        for (int kk = 0; kk < 64; kk++) {
            float4 a = *(const float4*)&bufA[kk*68 + ty*4];
            float4 b = *(const float4*)&bufB[kk*68 + tx*4];
            acc[0][0] = fmaf(a.x, b.x, acc[0][0]); acc[0][1] = fmaf(a.x, b.y, acc[0][1]);
            acc[0][2] = fmaf(a.x, b.z, acc[0][2]); acc[0][3] = fmaf(a.x, b.w, acc[0][3]);
            acc[1][0] = fmaf(a.y, b.x, acc[1][0]); acc[1][1] = fmaf(a.y, b.y, acc[1][1]);
            acc[1][2] = fmaf(a.y, b.z, acc[1][2]); acc[1][3] = fmaf(a.y, b.w, acc[1][3]);
            acc[2][0] = fmaf(a.z, b.x, acc[2][0]); acc[2][1] = fmaf(a.z, b.y, acc[2][1]);
            acc[2][2] = fmaf(a.z, b.z, acc[2][2]); acc[2][3] = fmaf(a.z, b.w, acc[2][3]);
            acc[3][0] = fmaf(a.w, b.x, acc[3][0]); acc[3][1] = fmaf(a.w, b.y, acc[3][1]);
            acc[3][2] = fmaf(a.w, b.z, acc[3][2]); acc[3][3] = fmaf(a.w, b.w, acc[3][3]);
        }
        __syncthreads();
    }
    // xpT into bufA (overwrite xT)
#pragma unroll
    for (int r = 0; r < 4; r++)
#pragma unroll
        for (int c = 0; c < 4; c++)
            bufA[(tx*4 + c)*68 + (ty*4 + r)] = acc[r][c] + bp[tx*4 + c];
    __syncthreads();

    const float* Ws[3] = {Wq, Wk, Wv};
    const float* bs[3] = {bq, bk, bv};
    float* outs[3] = {g_q, g_k, g_v};
    for (int t = 0; t < 3; t++) {
        for (int idx = tid; idx < 4096; idx += 256) {
            int kk = idx >> 6, j = idx & 63;
            bufB[kk*68 + j] = Ws[t][kk*DD + j];
        }
        __syncthreads();
        float o[4][4];
#pragma unroll
        for (int r = 0; r < 4; r++)
#pragma unroll
            for (int c = 0; c < 4; c++) o[r][c] = 0.f;
#pragma unroll 8
        for (int kk = 0; kk < 64; kk++) {
            float4 a = *(const float4*)&bufA[kk*68 + ty*4];
            float4 b = *(const float4*)&bufB[kk*68 + tx*4];
            o[0][0] = fmaf(a.x, b.x, o[0][0]); o[0][1] = fmaf(a.x, b.y, o[0][1]);
            o[0][2] = fmaf(a.x, b.z, o[0][2]); o[0][3] = fmaf(a.x, b.w, o[0][3]);
            o[1][0] = fmaf(a.y, b.x, o[1][0]); o[1][1] = fmaf(a.y, b.y, o[1][1]);
            o[1][2] = fmaf(a.y, b.z, o[1][2]); o[1][3] = fmaf(a.y, b.w, o[1][3]);
            o[2][0] = fmaf(a.z, b.x, o[2][0]); o[2][1] = fmaf(a.z, b.y, o[2][1]);
            o[2][2] = fmaf(a.z, b.z, o[2][2]); o[2][3] = fmaf(a.z, b.w, o[2][3]);
            o[3][0] = fmaf(a.w, b.x, o[3][0]); o[3][1] = fmaf(a.w, b.y, o[3][1]);
            o[3][2] = fmaf(a.w, b.z, o[3][2]); o[3][3] = fmaf(a.w, b.w, o[3][3]);
        }
#pragma unroll
        for (int r = 0; r < 4; r++) {
            float4 v4;
            v4.x = o[r][0] + bs[t][tx*4 + 0];
            v4.y = o[r][1] + bs[t][tx*4 + 1];
            v4.z = o[r][2] + bs[t][tx*4 + 2];
            v4.w = o[r][3] + bs[t][tx*4 + 3];
            *(float4*)&outs[t][(row0 + ty*4 + r)*DD + tx*4] = v4;
        }
        __syncthreads();
    }
}

// ============================================================
// Kernel 2: fused attention (scores*rel, softmax, PV) + FFN + LN + head.
// Grid (8, 16): one CTA per (b, 64-query tile). 256 threads.
// Dynamic smem: S[64][512] + qT + kv chunk + rel + ranks  (~168 KB).
// FFN stages reuse the S region.
// ============================================================
#define SMEM_FLOATS (32768 + 4352 + 4352 + 64 + 512)
#define SMEM_BYTES  (SMEM_FLOATS * 4)

__global__ __launch_bounds__(256) void attn_kernel(
    const int* __restrict__ ranks,
    const float* __restrict__ Wf1, const float* __restrict__ bf1,
    const float* __restrict__ Wf2, const float* __restrict__ bf2,
    const float* __restrict__ ln_g, const float* __restrict__ ln_b,
    const float* __restrict__ Ws1, const float* __restrict__ bs1,
    const float* __restrict__ Ws2, const float* __restrict__ bs2,
    float* __restrict__ out) {
    extern __shared__ float sm[];
    float* S   = sm;                          // 64*512
    float* qT  = sm + 32768;                  // 64*68
    float* kv  = sm + 32768 + 4352;           // 64*68
    float* rel = sm + 32768 + 8704;           // 51 (padded 64)
    int*   rk  = (int*)(sm + 32768 + 8704 + 64);  // 512

    const int tid = threadIdx.x;
    const int ty = tid >> 4, tx = tid & 15;
    const int b = blockIdx.y;
    const int q0 = blockIdx.x * 64;
    const int base = b * NN;

    if (tid <= MAXDIST) rel[tid] = g_rel[tid];
    for (int m = tid; m < NN; m += 256) rk[m] = ranks[base + m];
    for (int idx = tid; idx < 4096; idx += 256) {
        int i = idx >> 6, d = idx & 63;
        qT[d*68 + i] = g_q[(base + q0 + i)*DD + d];
    }
    __syncthreads();

    // ---- Phase 1: S = (Q K^T / 8) * rel(dist) ----
    int ri[4];
#pragma unroll
    for (int r = 0; r < 4; r++) ri[r] = rk[q0 + ty*4 + r];

    for (int mc = 0; mc < 8; mc++) {
        for (int idx = tid; idx < 4096; idx += 256) {
            int ml = idx >> 6, d = idx & 63;
            kv[d*68 + ml] = g_k[(base + mc*64 + ml)*DD + d];   // kT
        }
        __syncthreads();
        float acc[4][4];
#pragma unroll
        for (int r = 0; r < 4; r++)
#pragma unroll
            for (int c = 0; c < 4; c++) acc[r][c] = 0.f;
#pragma unroll 8
        for (int d = 0; d < 64; d++) {
            float4 a = *(const float4*)&qT[d*68 + ty*4];
            float4 bb = *(const float4*)&kv[d*68 + tx*4];
            acc[0][0] = fmaf(a.x, bb.x, acc[0][0]); acc[0][1] = fmaf(a.x, bb.y, acc[0][1]);
            acc[0][2] = fmaf(a.x, bb.z, acc[0][2]); acc[0][3] = fmaf(a.x, bb.w, acc[0][3]);
            acc[1][0] = fmaf(a.y, bb.x, acc[1][0]); acc[1][1] = fmaf(a.y, bb.y, acc[1][1]);
            acc[1][2] = fmaf(a.y, bb.z, acc[1][2]); acc[1][3] = fmaf(a.y, bb.w, acc[1][3]);
            acc[2][0] = fmaf(a.z, bb.x, acc[2][0]); acc[2][1] = fmaf(a.z, bb.y, acc[2][1]);
            acc[2][2] = fmaf(a.z, bb.z, acc[2][2]); acc[2][3] = fmaf(a.z, bb.w, acc[2][3]);
            acc[3][0] = fmaf(a.w, bb.x, acc[3][0]); acc[3][1] = fmaf(a.w, bb.y, acc[3][1]);
            acc[3][2] = fmaf(a.w, bb.z, acc[3][2]); acc[3][3] = fmaf(a.w, bb.w, acc[3][3]);
        }
#pragma unroll
        for (int r = 0; r < 4; r++)
#pragma unroll
            for (int c = 0; c < 4; c++) {
                int m = mc*64 + tx*4 + c;
                int dd = ri[r] - rk[m]; if (dd < 0) dd = -dd; if (dd > MAXDIST) dd = MAXDIST;
                S[(ty*4 + r)*NN + m] = acc[r][c] * 0.125f * rel[dd];
            }
        __syncthreads();
    }

    // ---- Phase 2: row softmax ----
    {
        const int warp = tid >> 5, lane = tid & 31;
        for (int rr = 0; rr < 8; rr++) {
            float* Sr = S + (warp*8 + rr)*NN;
            float mx = -1e30f;
            for (int m = lane; m < NN; m += 32) mx = fmaxf(mx, Sr[m]);
#pragma unroll
            for (int o = 16; o >= 1; o >>= 1) mx = fmaxf(mx, __shfl_xor_sync(0xffffffffu, mx, o));
            float sum = 0.f;
            for (int m = lane; m < NN; m += 32) { float e = __expf(Sr[m] - mx); Sr[m] = e; sum += e; }
#pragma unroll
            for (int o = 16; o >= 1; o >>= 1) sum += __shfl_xor_sync(0xffffffffu, sum, o);
            float inv = 1.f / sum;
            for (int m = lane; m < NN; m += 32) Sr[m] *= inv;
        }
    }
    __syncthreads();

    // ---- Phase 3: AO = P @ V ----
    float C[4][4];
#pragma unroll
    for (int r = 0; r < 4; r++)
#pragma unroll
        for (int c = 0; c < 4; c++) C[r][c] = 0.f;
    for (int mc = 0; mc < 8; mc++) {
        for (int idx = tid; idx < 4096; idx += 256) {
            int ml = idx >> 6, d = idx & 63;
            kv[ml*68 + d] = g_v[(base + mc*64 + ml)*DD + d];   // row-major v chunk
        }
        __syncthreads();
#pragma unroll 4
        for (int ml = 0; ml < 64; ml++) {
            int m = mc*64 + ml;
            float4 bv4 = *(const float4*)&kv[ml*68 + tx*4];
#pragma unroll
            for (int r = 0; r < 4; r++) {
                float a = S[(ty*4 + r)*NN + m];
                C[r][0] = fmaf(a, bv4.x, C[r][0]);
                C[r][1] = fmaf(a, bv4.y, C[r][1]);
                C[r][2] = fmaf(a, bv4.z, C[r][2]);
                C[r][3] = fmaf(a, bv4.w, C[r][3]);
            }
        }
        __syncthreads();
    }

    // ---- Phase 4: FFN + LN + head (reuse S region) ----
    float* aoT = sm;           // 4352 floats
    float* w1  = sm + 4352;    // 8192 floats
#pragma unroll
    for (int r = 0; r < 4; r++)
#pragma unroll
        for (int c = 0; c < 4; c++)
            aoT[(tx*4 + c)*68 + ty*4 + r] = C[r][c];
    for (int idx = tid; idx < 8192; idx += 256) w1[idx] = Wf1[idx];
    __syncthreads();

    // h1 = relu(ao @ Wf1 + bf1): 64x128, per-thread 4x8
    float h1v[4][8];
#pragma unroll
    for (int r = 0; r < 4; r++)
#pragma unroll
        for (int c = 0; c < 8; c++) h1v[r][c] = 0.f;
#pragma unroll 4
    for (int kk = 0; kk < 64; kk++) {
        float4 a = *(const float4*)&aoT[kk*68 + ty*4];
        float4 b0 = *(const float4*)&w1[kk*128 + tx*8];
        float4 b1 = *(const float4*)&w1[kk*128 + tx*8 + 4];
        float av[4] = {a.x, a.y, a.z, a.w};
        float bv[8] = {b0.x, b0.y, b0.z, b0.w, b1.x, b1.y, b1.z, b1.w};
#pragma unroll
        for (int r = 0; r < 4; r++)
#pragma unroll
            for (int c = 0; c < 8; c++) h1v[r][c] = fmaf(av[r], bv[c], h1v[r][c]);
    }
#pragma unroll
    for (int r = 0; r < 4; r++)
#pragma unroll
        for (int c = 0; c < 8; c++) h1v[r][c] = fmaxf(h1v[r][c] + bf1[tx*8 + c], 0.f);
    __syncthreads();

    float* h1T = sm;           // 128*68 = 8704 floats
    float* w2  = sm + 8704;    // 8192 floats
#pragma unroll
    for (int r = 0; r < 4; r++)
#pragma unroll
        for (int c = 0; c < 8; c++)
            h1T[(tx*8 + c)*68 + ty*4 + r] = h1v[r][c];
    for (int idx = tid; idx < 8192; idx += 256) w2[idx] = Wf2[idx];
    __syncthreads();

    // h2 = h1 @ Wf2 + bf2: 64x64
    float h2[4][4];
#pragma unroll
    for (int r = 0; r < 4; r++)
#pragma unroll
        for (int c = 0; c < 4; c++) h2[r][c] = 0.f;
#pragma unroll 4
    for (int kk = 0; kk < 128; kk++) {
        float4 a = *(const float4*)&h1T[kk*68 + ty*4];
        float4 bb = *(const float4*)&w2[kk*64 + tx*4];
        h2[0][0] = fmaf(a.x, bb.x, h2[0][0]); h2[0][1] = fmaf(a.x, bb.y, h2[0][1]);
        h2[0][2] = fmaf(a.x, bb.z, h2[0][2]); h2[0][3] = fmaf(a.x, bb.w, h2[0][3]);
        h2[1][0] = fmaf(a.y, bb.x, h2[1][0]); h2[1][1] = fmaf(a.y, bb.y, h2[1][1]);
        h2[1][2] = fmaf(a.y, bb.z, h2[1][2]); h2[1][3] = fmaf(a.y, bb.w, h2[1][3]);
        h2[2][0] = fmaf(a.z, bb.x, h2[2][0]); h2[2][1] = fmaf(a.z, bb.y, h2[2][1]);
        h2[2][2] = fmaf(a.z, bb.z, h2[2][2]); h2[2][3] = fmaf(a.z, bb.w, h2[2][3]);
        h2[3][0] = fmaf(a.w, bb.x, h2[3][0]); h2[3][1] = fmaf(a.w, bb.y, h2[3][1]);
        h2[3][2] = fmaf(a.w, bb.z, h2[3][2]); h2[3][3] = fmaf(a.w, bb.w, h2[3][3]);
    }
    float gcol[4], bcol[4];
#pragma unroll
    for (int c = 0; c < 4; c++) {
        h2[0][c] += bf2[tx*4 + c]; h2[1][c] += bf2[tx*4 + c];
        h2[2][c] += bf2[tx*4 + c]; h2[3][c] += bf2[tx*4 + c];
        gcol[c] = ln_g[tx*4 + c]; bcol[c] = ln_b[tx*4 + c];
    }
    // LayerNorm: reduce over 16 threads sharing the row group (lanes 0-15 / 16-31)
    float hn[4][4];
#pragma unroll
    for (int r = 0; r < 4; r++) {
        float s = h2[r][0] + h2[r][1] + h2[r][2] + h2[r][3];
        float s2 = h2[r][0]*h2[r][0] + h2[r][1]*h2[r][1] + h2[r][2]*h2[r][2] + h2[r][3]*h2[r][3];
#pragma unroll
        for (int o = 8; o >= 1; o >>= 1) {
            s  += __shfl_xor_sync(0xffffffffu, s,  o, 16);
            s2 += __shfl_xor_sync(0xffffffffu, s2, o, 16);
        }
        float mu = s * (1.f/64.f);
        float var = s2 * (1.f/64.f) - mu*mu;
        float inv = rsqrtf(var + 1e-5f);
#pragma unroll
        for (int c = 0; c < 4; c++)
            hn[r][c] = (h2[r][c] - mu) * inv * gcol[c] + bcol[c];
    }
    __syncthreads();

    float* hnT = sm;           // 4352
    float* ws1 = sm + 4352;    // 2048
    float* ws2 = sm + 6400;    // 32
#pragma unroll
    for (int r = 0; r < 4; r++)
#pragma unroll
        for (int c = 0; c < 4; c++)
            hnT[(tx*4 + c)*68 + ty*4 + r] = hn[r][c];
    for (int idx = tid; idx < 2048; idx += 256) ws1[idx] = Ws1[idx];
    if (tid < 32) ws2[tid] = Ws2[tid];
    __syncthreads();

    // s1 = relu(hn @ Ws1 + bs1): 64x32, per-thread 4x2; then @Ws2 + bs2, sigmoid
    float s1[4][2];
#pragma unroll
    for (int r = 0; r < 4; r++) { s1[r][0] = 0.f; s1[r][1] = 0.f; }
#pragma unroll 4
    for (int kk = 0; kk < 64; kk++) {
        float4 a = *(const float4*)&hnT[kk*68 + ty*4];
        float b0 = ws1[kk*32 + tx*2], b1 = ws1[kk*32 + tx*2 + 1];
        s1[0][0] = fmaf(a.x, b0, s1[0][0]); s1[0][1] = fmaf(a.x, b1, s1[0][1]);
        s1[1][0] = fmaf(a.y, b0, s1[1][0]); s1[1][1] = fmaf(a.y, b1, s1[1][1]);
        s1[2][0] = fmaf(a.z, b0, s1[2][0]); s1[2][1] = fmaf(a.z, b1, s1[2][1]);
        s1[3][0] = fmaf(a.w, b0, s1[3][0]); s1[3][1] = fmaf(a.w, b1, s1[3][1]);
    }
    float w2a = ws2[tx*2], w2b = ws2[tx*2 + 1];
    float bs1a = bs1[tx*2], bs1b = bs1[tx*2 + 1];
    float bs2v = bs2[0];
#pragma unroll
    for (int r = 0; r < 4; r++) {
        float pa = fmaxf(s1[r][0] + bs1a, 0.f);
        float pb = fmaxf(s1[r][1] + bs1b, 0.f);
        float p = pa*w2a + pb*w2b;
#pragma unroll
        for (int o = 8; o >= 1; o >>= 1) p += __shfl_xor_sync(0xffffffffu, p, o, 16);
        if (tx == 0) {
            float z = p + bs2v;
            out[base + q0 + ty*4 + r] = 1.f / (1.f + __expf(-z));
        }
    }
}

// ============================================================
extern "C" void kernel_launch(void* const* d_in, const int* in_sizes, int n_in,
                              void* d_out, int out_size) {
    const float* x     = (const float*)d_in[0];
    const int*   ranks = (const int*)  d_in[1];
    const float* Wp    = (const float*)d_in[2];
    const float* bp    = (const float*)d_in[3];
    const float* Wq    = (const float*)d_in[4];
    const float* bq    = (const float*)d_in[5];
    const float* Wk    = (const float*)d_in[6];
    const float* bk    = (const float*)d_in[7];
    const float* Wv    = (const float*)d_in[8];
    const float* bv    = (const float*)d_in[9];
    const float* Eemb  = (const float*)d_in[10];
    const float* Wr1   = (const float*)d_in[11];
    const float* br1   = (const float*)d_in[12];
    const float* Wr2   = (const float*)d_in[13];
    const float* Wf1   = (const float*)d_in[14];
    const float* bf1   = (const float*)d_in[15];
    const float* Wf2   = (const float*)d_in[16];
    const float* bf2   = (const float*)d_in[17];
    const float* ln_g  = (const float*)d_in[18];
    const float* ln_b  = (const float*)d_in[19];
    const float* Ws1   = (const float*)d_in[20];
    const float* bs1   = (const float*)d_in[21];
    const float* Ws2   = (const float*)d_in[22];
    const float* bs2   = (const float*)d_in[23];
    float* out = (float*)d_out;

    cudaFuncSetAttribute(attn_kernel, cudaFuncAttributeMaxDynamicSharedMemorySize, SMEM_BYTES);

    rel_table_kernel<<<1, 64>>>(Eemb, Wr1, br1, Wr2);
    qkv_kernel<<<BB*NN/64, 256>>>(x, Wp, bp, Wq, bq, Wk, bk, Wv, bv);
    dim3 grid(NN/64, BB);
    attn_kernel<<<grid, 256, SMEM_BYTES>>>(ranks, Wf1, bf1, Wf2, bf2,
                                           ln_g, ln_b, Ws1, bs1, Ws2, bs2, out);
}

// round 2
// speedup vs baseline: 1.3180x; 1.3180x over previous
#include <cuda_runtime.h>

#define BB   16
#define NN   512
#define DIN  256
#define DD   64
#define EE   32
#define MAXDIST 50

// -------- scratch (no allocations allowed) --------
__device__ float g_qT[BB*DD*NN];   // per batch: [d][n]
__device__ float g_kT[BB*DD*NN];   // per batch: [d][n]
__device__ float g_v [BB*NN*DD];   // row-major [n][d]
__device__ float g_rel[MAXDIST+1];

// ============================================================
// Kernel 1: xp = x@Wp+bp ; q,k,v = xp@W{q,k,v}+b (fused),
// q,k written transposed per batch. Block 0 also computes the
// 51-entry rel table: rel[d]=sigmoid(relu(Eemb[d]@Wr1+br1)@Wr2).
// One CTA = 64 rows, 256 threads, 4x4 tiles, prefetch double-buffer.
// ============================================================
__global__ __launch_bounds__(256) void qkv_kernel(
    const float* __restrict__ x,
    const float* __restrict__ Wp, const float* __restrict__ bp,
    const float* __restrict__ Wq, const float* __restrict__ bq,
    const float* __restrict__ Wk, const float* __restrict__ bk,
    const float* __restrict__ Wv, const float* __restrict__ bv,
    const float* __restrict__ Eemb, const float* __restrict__ Wr1,
    const float* __restrict__ br1,  const float* __restrict__ Wr2) {
    __shared__ float bufA[64*68];   // xT chunk, later xpT
    __shared__ float bufB[64*68];   // weight chunk
    const int tid = threadIdx.x;
    const int ty = tid >> 4, tx = tid & 15;
    const int row0 = blockIdx.x * 64;
    const int b = row0 >> 9;
    const int n0 = row0 & 511;

    // --- rel table (block 0 only, overlapped with GEMM work) ---
    if (blockIdx.x == 0 && tid <= MAXDIST) {
        float e[EE];
#pragma unroll
        for (int c = 0; c < EE; c++) e[c] = Eemb[tid*EE + c];
        float w = 0.f;
#pragma unroll
        for (int j = 0; j < 16; j++) {
            float h = br1[j];
#pragma unroll
            for (int c = 0; c < EE; c++) h = fmaf(e[c], Wr1[c*16 + j], h);
            h = fmaxf(h, 0.f);
            w = fmaf(h, Wr2[j], w);
        }
        g_rel[tid] = 1.f / (1.f + __expf(-w));
    }

    // --- xp = x @ Wp, K-chunks of 64 with register prefetch ---
    float ra[16], rb[16];
#pragma unroll
    for (int j = 0; j < 16; j++) {
        int idx = tid + j*256;
        ra[j] = x[(row0 + (idx >> 6))*DIN + (idx & 63)];
        rb[j] = Wp[(idx >> 6)*DD + (idx & 63)];
    }
    float acc[4][4];
#pragma unroll
    for (int r = 0; r < 4; r++)
#pragma unroll
        for (int c = 0; c < 4; c++) acc[r][c] = 0.f;

    for (int kc = 0; kc < 4; kc++) {
#pragma unroll
        for (int j = 0; j < 16; j++) {
            int idx = tid + j*256;
            bufA[(idx & 63)*68 + (idx >> 6)] = ra[j];   // x transposed
            bufB[(idx >> 6)*68 + (idx & 63)] = rb[j];
        }
        __syncthreads();
        if (kc < 3) {
#pragma unroll
            for (int j = 0; j < 16; j++) {
                int idx = tid + j*256;
                ra[j] = x[(row0 + (idx >> 6))*DIN + (kc+1)*64 + (idx & 63)];
                rb[j] = Wp[((kc+1)*64 + (idx >> 6))*DD + (idx & 63)];
            }
        }
#pragma unroll 8
        for (int kk = 0; kk < 64; kk++) {
            float4 a = *(const float4*)&bufA[kk*68 + ty*4];
            float4 bv4 = *(const float4*)&bufB[kk*68 + tx*4];
            acc[0][0] = fmaf(a.x, bv4.x, acc[0][0]); acc[0][1] = fmaf(a.x, bv4.y, acc[0][1]);
            acc[0][2] = fmaf(a.x, bv4.z, acc[0][2]); acc[0][3] = fmaf(a.x, bv4.w, acc[0][3]);
            acc[1][0] = fmaf(a.y, bv4.x, acc[1][0]); acc[1][1] = fmaf(a.y, bv4.y, acc[1][1]);
            acc[1][2] = fmaf(a.y, bv4.z, acc[1][2]); acc[1][3] = fmaf(a.y, bv4.w, acc[1][3]);
            acc[2][0] = fmaf(a.z, bv4.x, acc[2][0]); acc[2][1] = fmaf(a.z, bv4.y, acc[2][1]);
            acc[2][2] = fmaf(a.z, bv4.z, acc[2][2]); acc[2][3] = fmaf(a.z, bv4.w, acc[2][3]);
            acc[3][0] = fmaf(a.w, bv4.x, acc[3][0]); acc[3][1] = fmaf(a.w, bv4.y, acc[3][1]);
            acc[3][2] = fmaf(a.w, bv4.z, acc[3][2]); acc[3][3] = fmaf(a.w, bv4.w, acc[3][3]);
        }
        __syncthreads();
    }
    // xpT into bufA
#pragma unroll
    for (int r = 0; r < 4; r++)
#pragma unroll
        for (int c = 0; c < 4; c++)
            bufA[(tx*4 + c)*68 + (ty*4 + r)] = acc[r][c] + bp[tx*4 + c];
    __syncthreads();

    const float* Ws[3] = {Wq, Wk, Wv};
    const float* bs[3] = {bq, bk, bv};
    for (int t = 0; t < 3; t++) {
#pragma unroll
        for (int j = 0; j < 16; j++) {
            int idx = tid + j*256;
            bufB[(idx >> 6)*68 + (idx & 63)] = Ws[t][idx];
        }
        __syncthreads();
        float o[4][4];
#pragma unroll
        for (int r = 0; r < 4; r++)
#pragma unroll
            for (int c = 0; c < 4; c++) o[r][c] = 0.f;
#pragma unroll 8
        for (int kk = 0; kk < 64; kk++) {
            float4 a = *(const float4*)&bufA[kk*68 + ty*4];
            float4 bv4 = *(const float4*)&bufB[kk*68 + tx*4];
            o[0][0] = fmaf(a.x, bv4.x, o[0][0]); o[0][1] = fmaf(a.x, bv4.y, o[0][1]);
            o[0][2] = fmaf(a.x, bv4.z, o[0][2]); o[0][3] = fmaf(a.x, bv4.w, o[0][3]);
            o[1][0] = fmaf(a.y, bv4.x, o[1][0]); o[1][1] = fmaf(a.y, bv4.y, o[1][1]);
            o[1][2] = fmaf(a.y, bv4.z, o[1][2]); o[1][3] = fmaf(a.y, bv4.w, o[1][3]);
            o[2][0] = fmaf(a.z, bv4.x, o[2][0]); o[2][1] = fmaf(a.z, bv4.y, o[2][1]);
            o[2][2] = fmaf(a.z, bv4.z, o[2][2]); o[2][3] = fmaf(a.z, bv4.w, o[2][3]);
            o[3][0] = fmaf(a.w, bv4.x, o[3][0]); o[3][1] = fmaf(a.w, bv4.y, o[3][1]);
            o[3][2] = fmaf(a.w, bv4.z, o[3][2]); o[3][3] = fmaf(a.w, bv4.w, o[3][3]);
        }
        if (t == 2) {
            // v row-major
#pragma unroll
            for (int r = 0; r < 4; r++) {
                float4 v4;
                v4.x = o[r][0] + bs[2][tx*4 + 0];
                v4.y = o[r][1] + bs[2][tx*4 + 1];
                v4.z = o[r][2] + bs[2][tx*4 + 2];
                v4.w = o[r][3] + bs[2][tx*4 + 3];
                *(float4*)&g_v[(row0 + ty*4 + r)*DD + tx*4] = v4;
            }
        } else {
            // q, k transposed per batch: [d][n]
            float* dst = (t == 0) ? g_qT : g_kT;
#pragma unroll
            for (int r = 0; r < 4; r++)
#pragma unroll
                for (int c = 0; c < 4; c++)
                    dst[b*DD*NN + (tx*4 + c)*NN + n0 + ty*4 + r] = o[r][c] + bs[t][tx*4 + c];
        }
        __syncthreads();
    }
}

// ============================================================
// Kernel 2: fused attention + FFN + LN + head. 512 threads.
// Grid (8,16): one CTA per (b, 64-query tile).
// ============================================================
#define S_STRIDE 516
#define R1_OFF   33024            /* 64*516; region: kT / vbuf / aoT+w1 / w2 / ws1+ws2 (16640 f) */
#define R2_OFF   49664            /* region: qT / po / hnT (4352 f) */
#define REL_OFF  54016
#define RK_OFF   54080
#define SMEM_FLOATS 54592
#define SMEM_BYTES  (SMEM_FLOATS*4)

__global__ __launch_bounds__(512) void attn_kernel(
    const int* __restrict__ ranks,
    const float* __restrict__ Wf1, const float* __restrict__ bf1,
    const float* __restrict__ Wf2, const float* __restrict__ bf2,
    const float* __restrict__ ln_g, const float* __restrict__ ln_b,
    const float* __restrict__ Ws1, const float* __restrict__ bs1,
    const float* __restrict__ Ws2, const float* __restrict__ bs2,
    float* __restrict__ out) {
    extern __shared__ float sm[];
    float* S   = sm;
    float* R1  = sm + R1_OFF;
    float* R2  = sm + R2_OFF;
    float* rel = sm + REL_OFF;
    int*   rk  = (int*)(sm + RK_OFF);

    const int tid = threadIdx.x;
    const int b = blockIdx.y;
    const int q0 = blockIdx.x * 64;
    const int base = b * NN;
    const int bT = b * DD * NN;

    // ---- stage rel, ranks, qT ----
    if (tid <= MAXDIST) rel[tid] = g_rel[tid];
    for (int m = tid; m < NN; m += 512) rk[m] = ranks[base + m];
#pragma unroll
    for (int j = 0; j < 8; j++) {
        int idx = tid + j*512;
        int d = idx >> 6, i = idx & 63;
        R2[d*68 + i] = g_qT[bT + d*NN + q0 + i];     // qT[d][i]
    }
    __syncthreads();

    // ---- Phase 1: S = (QK^T/8)*rel, key chunks of 256 ----
    {
        const int ty = tid >> 6;        // 0..7  -> 8 rows each
        const int tx = tid & 63;        // 0..63 -> 4 cols each
        int ri[8];
#pragma unroll
        for (int rr = 0; rr < 8; rr++) ri[rr] = rk[q0 + ty*8 + rr];

        for (int kc = 0; kc < 2; kc++) {
            const int k0 = kc * 256;
#pragma unroll
            for (int j = 0; j < 32; j++) {          // stage kT chunk: [d][key] stride 260
                int idx = tid + j*512;
                int d = idx >> 8, key = idx & 255;
                R1[d*260 + key] = g_kT[bT + d*NN + k0 + key];
            }
            __syncthreads();
            float acc[8][4];
#pragma unroll
            for (int rr = 0; rr < 8; rr++)
#pragma unroll
                for (int c = 0; c < 4; c++) acc[rr][c] = 0.f;
#pragma unroll 4
            for (int d = 0; d < 64; d++) {
                float4 a0 = *(const float4*)&R2[d*68 + ty*8];
                float4 a1 = *(const float4*)&R2[d*68 + ty*8 + 4];
                float4 kb = *(const float4*)&R1[d*260 + tx*4];
                float av[8] = {a0.x,a0.y,a0.z,a0.w,a1.x,a1.y,a1.z,a1.w};
#pragma unroll
                for (int rr = 0; rr < 8; rr++) {
                    acc[rr][0] = fmaf(av[rr], kb.x, acc[rr][0]);
                    acc[rr][1] = fmaf(av[rr], kb.y, acc[rr][1]);
                    acc[rr][2] = fmaf(av[rr], kb.z, acc[rr][2]);
                    acc[rr][3] = fmaf(av[rr], kb.w, acc[rr][3]);
                }
            }
            int rkc[4];
#pragma unroll
            for (int c = 0; c < 4; c++) rkc[c] = rk[k0 + tx*4 + c];
#pragma unroll
            for (int rr = 0; rr < 8; rr++) {
                float4 o;
                float* oc = (float*)&o;
#pragma unroll
                for (int c = 0; c < 4; c++) {
                    int dd = ri[rr] - rkc[c]; if (dd < 0) dd = -dd; if (dd > MAXDIST) dd = MAXDIST;
                    oc[c] = acc[rr][c] * 0.125f * rel[dd];
                }
                *(float4*)&S[(ty*8 + rr)*S_STRIDE + k0 + tx*4] = o;
            }
            __syncthreads();
        }
    }

    // ---- Phase 2: row softmax (16 warps x 4 rows) ----
    {
        const int warp = tid >> 5, lane = tid & 31;
#pragma unroll
        for (int rr = 0; rr < 4; rr++) {
            float* Sr = S + (warp*4 + rr)*S_STRIDE;
            float mx = -1e30f;
#pragma unroll
            for (int j = 0; j < 16; j++) mx = fmaxf(mx, Sr[lane + j*32]);
#pragma unroll
            for (int o = 16; o >= 1; o >>= 1) mx = fmaxf(mx, __shfl_xor_sync(0xffffffffu, mx, o));
            float sum = 0.f;
#pragma unroll
            for (int j = 0; j < 16; j++) {
                float e = __expf(Sr[lane + j*32] - mx);
                Sr[lane + j*32] = e; sum += e;
            }
#pragma unroll
            for (int o = 16; o >= 1; o >>= 1) sum += __shfl_xor_sync(0xffffffffu, sum, o);
            float inv = 1.f / sum;
#pragma unroll
            for (int j = 0; j < 16; j++) Sr[lane + j*32] *= inv;
        }
    }
    __syncthreads();

    // ---- Phase 3: AO = P@V, split-K over 2 groups of 256 threads ----
    float acc3[4][4];
#pragma unroll
    for (int r = 0; r < 4; r++)
#pragma unroll
        for (int c = 0; c < 4; c++) acc3[r][c] = 0.f;
    {
        const int g   = tid >> 8;          // 0,1
        const int t   = tid & 255;
        const int tyv = t >> 4, txv = t & 15;   // 4 rows x 4 cols
        for (int rnd = 0; rnd < 2; rnd++) {
            // stage v chunk pair: keys rnd*256 .. rnd*256+255, row-major [key][d] stride 64
#pragma unroll
            for (int j = 0; j < 32; j++) {
                int idx = tid + j*512;
                int key = idx >> 6, d = idx & 63;
                R1[key*64 + d] = g_v[(base + rnd*256 + key)*DD + d];
            }
            __syncthreads();
            const int goff = g * 128;                 // into staged keys
            const int kbase = rnd*256 + g*128;        // into S cols
#pragma unroll 2
            for (int ml = 0; ml < 128; ml += 4) {
                float4 p4[4];
#pragma unroll
                for (int rr = 0; rr < 4; rr++)
                    p4[rr] = *(const float4*)&S[(tyv*4 + rr)*S_STRIDE + kbase + ml];
                float4 v4[4];
#pragma unroll
                for (int j = 0; j < 4; j++)
                    v4[j] = *(const float4*)&R1[(goff + ml + j)*64 + txv*4];
#pragma unroll
                for (int rr = 0; rr < 4; rr++) {
                    float pv[4] = {p4[rr].x, p4[rr].y, p4[rr].z, p4[rr].w};
#pragma unroll
                    for (int j = 0; j < 4; j++) {
                        acc3[rr][0] = fmaf(pv[j], v4[j].x, acc3[rr][0]);
                        acc3[rr][1] = fmaf(pv[j], v4[j].y, acc3[rr][1]);
                        acc3[rr][2] = fmaf(pv[j], v4[j].z, acc3[rr][2]);
                        acc3[rr][3] = fmaf(pv[j], v4[j].w, acc3[rr][3]);
                    }
                }
            }
            __syncthreads();
        }
        // reduce group 1 into group 0 via R2 (qT dead)
        if (g == 1) {
#pragma unroll
            for (int rr = 0; rr < 4; rr++) {
                float4 o = {acc3[rr][0], acc3[rr][1], acc3[rr][2], acc3[rr][3]};
                *(float4*)&R2[(tyv*4 + rr)*64 + txv*4] = o;
            }
        }
        __syncthreads();
        if (g == 0) {
#pragma unroll
            for (int rr = 0; rr < 4; rr++) {
                float4 o = *(const float4*)&R2[(tyv*4 + rr)*64 + txv*4];
                acc3[rr][0] += o.x; acc3[rr][1] += o.y; acc3[rr][2] += o.z; acc3[rr][3] += o.w;
            }
        }
        __syncthreads();
        // group 0 writes aoT [d][row] stride 68 into R1 (vbuf dead)
        if (g == 0) {
#pragma unroll
            for (int rr = 0; rr < 4; rr++)
#pragma unroll
                for (int c = 0; c < 4; c++)
                    R1[(txv*4 + c)*68 + tyv*4 + rr] = acc3[rr][c];
        }
    }
    // stage w1 into R1+4352
    float* w1 = R1 + 4352;
#pragma unroll
    for (int j = 0; j < 16; j++) w1[tid + j*512] = Wf1[tid + j*512];
    __syncthreads();

    // ---- Phase 4a: h1 = relu(ao@Wf1+bf1)  (64x128) ----
    float h1v[4][4];
    {
        const int ty = tid >> 5, tx = tid & 31;     // rows ty*4, cols tx*4
#pragma unroll
        for (int r = 0; r < 4; r++)
#pragma unroll
            for (int c = 0; c < 4; c++) h1v[r][c] = 0.f;
#pragma unroll 4
        for (int kk = 0; kk < 64; kk++) {
            float4 a = *(const float4*)&R1[kk*68 + ty*4];
            float4 bw = *(const float4*)&w1[kk*128 + tx*4];
            h1v[0][0] = fmaf(a.x, bw.x, h1v[0][0]); h1v[0][1] = fmaf(a.x, bw.y, h1v[0][1]);
            h1v[0][2] = fmaf(a.x, bw.z, h1v[0][2]); h1v[0][3] = fmaf(a.x, bw.w, h1v[0][3]);
            h1v[1][0] = fmaf(a.y, bw.x, h1v[1][0]); h1v[1][1] = fmaf(a.y, bw.y, h1v[1][1]);
            h1v[1][2] = fmaf(a.y, bw.z, h1v[1][2]); h1v[1][3] = fmaf(a.y, bw.w, h1v[1][3]);
            h1v[2][0] = fmaf(a.z, bw.x, h1v[2][0]); h1v[2][1] = fmaf(a.z, bw.y, h1v[2][1]);
            h1v[2][2] = fmaf(a.z, bw.z, h1v[2][2]); h1v[2][3] = fmaf(a.z, bw.w, h1v[2][3]);
            h1v[3][0] = fmaf(a.w, bw.x, h1v[3][0]); h1v[3][1] = fmaf(a.w, bw.y, h1v[3][1]);
            h1v[3][2] = fmaf(a.w, bw.z, h1v[3][2]); h1v[3][3] = fmaf(a.w, bw.w, h1v[3][3]);
        }
#pragma unroll
        for (int r = 0; r < 4; r++)
#pragma unroll
            for (int c = 0; c < 4; c++)
                h1v[r][c] = fmaxf(h1v[r][c] + bf1[tx*4 + c], 0.f);
    }
    __syncthreads();
    // h1T into S region (stride 68), w2 into R1
    {
        const int ty = tid >> 5, tx = tid & 31;
#pragma unroll
        for (int r = 0; r < 4; r++)
#pragma unroll
            for (int c = 0; c < 4; c++)
                S[(tx*4 + c)*68 + ty*4 + r] = h1v[r][c];
#pragma unroll
        for (int j = 0; j < 16; j++) R1[tid + j*512] = Wf2[tid + j*512];
    }
    __syncthreads();

    // ---- Phase 4b: h2 = h1@Wf2+bf2, LayerNorm ----
    {
        const int ty = tid >> 5, tx = tid & 31;     // rows ty*4, cols tx*2
        float h2[4][2];
#pragma unroll
        for (int r = 0; r < 4; r++) { h2[r][0] = 0.f; h2[r][1] = 0.f; }
#pragma unroll 4
        for (int kk = 0; kk < 128; kk++) {
            float4 a = *(const float4*)&S[kk*68 + ty*4];
            float2 bw = *(const float2*)&R1[kk*64 + tx*2];
            h2[0][0] = fmaf(a.x, bw.x, h2[0][0]); h2[0][1] = fmaf(a.x, bw.y, h2[0][1]);
            h2[1][0] = fmaf(a.y, bw.x, h2[1][0]); h2[1][1] = fmaf(a.y, bw.y, h2[1][1]);
            h2[2][0] = fmaf(a.z, bw.x, h2[2][0]); h2[2][1] = fmaf(a.z, bw.y, h2[2][1]);
            h2[3][0] = fmaf(a.w, bw.x, h2[3][0]); h2[3][1] = fmaf(a.w, bw.y, h2[3][1]);
        }
        float b0 = bf2[tx*2], b1 = bf2[tx*2 + 1];
        float g0v = ln_g[tx*2], g1v = ln_g[tx*2 + 1];
        float be0 = ln_b[tx*2], be1 = ln_b[tx*2 + 1];
        __syncthreads();   // before overwriting R2 with hnT (po dead) & S reads done
#pragma unroll
        for (int r = 0; r < 4; r++) {
            float e0 = h2[r][0] + b0, e1 = h2[r][1] + b1;
            float s  = e0 + e1;
            float s2 = e0*e0 + e1*e1;
#pragma unroll
            for (int o = 16; o >= 1; o >>= 1) {
                s  += __shfl_xor_sync(0xffffffffu, s,  o);
                s2 += __shfl_xor_sync(0xffffffffu, s2, o);
            }
            float mu = s * (1.f/64.f);
            float var = s2 * (1.f/64.f) - mu*mu;
            float inv = rsqrtf(var + 1e-5f);
            R2[(tx*2 + 0)*68 + ty*4 + r] = (e0 - mu)*inv*g0v + be0;   // hnT
            R2[(tx*2 + 1)*68 + ty*4 + r] = (e1 - mu)*inv*g1v + be1;
        }
    }
    // stage ws1, ws2 into R1
    {
        for (int j = tid; j < 2048; j += 512) R1[j] = Ws1[j];
        if (tid < 32) R1[2048 + tid] = Ws2[tid];
    }
    __syncthreads();

    // ---- Phase 4c: head (threads 0..255) ----
    if (tid < 256) {
        const int ty = tid >> 4, tx = tid & 15;     // rows ty*4, cols tx*2
        float s1[4][2];
#pragma unroll
        for (int r = 0; r < 4; r++) { s1[r][0] = 0.f; s1[r][1] = 0.f; }
#pragma unroll 4
        for (int kk = 0; kk < 64; kk++) {
            float4 a = *(const float4*)&R2[kk*68 + ty*4];
            float w0 = R1[kk*32 + tx*2], w1b = R1[kk*32 + tx*2 + 1];
            s1[0][0] = fmaf(a.x, w0, s1[0][0]); s1[0][1] = fmaf(a.x, w1b, s1[0][1]);
            s1[1][0] = fmaf(a.y, w0, s1[1][0]); s1[1][1] = fmaf(a.y, w1b, s1[1][1]);
            s1[2][0] = fmaf(a.z, w0, s1[2][0]); s1[2][1] = fmaf(a.z, w1b, s1[2][1]);
            s1[3][0] = fmaf(a.w, w0, s1[3][0]); s1[3][1] = fmaf(a.w, w1b, s1[3][1]);
        }
        float w2a = R1[2048 + tx*2], w2b = R1[2048 + tx*2 + 1];
        float ba = bs1[tx*2], bb = bs1[tx*2 + 1];
        float bs2v = bs2[0];
#pragma unroll
        for (int r = 0; r < 4; r++) {
            float pa = fmaxf(s1[r][0] + ba, 0.f);
            float pb = fmaxf(s1[r][1] + bb, 0.f);
            float p = pa*w2a + pb*w2b;
#pragma unroll
            for (int o = 8; o >= 1; o >>= 1) p += __shfl_xor_sync(0xffffffffu, p, o, 16);
            if (tx == 0) {
                float z = p + bs2v;
                out[base + q0 + ty*4 + r] = 1.f / (1.f + __expf(-z));
            }
        }
    }
}

// ============================================================
extern "C" void kernel_launch(void* const* d_in, const int* in_sizes, int n_in,
                              void* d_out, int out_size) {
    const float* x     = (const float*)d_in[0];
    const int*   ranks = (const int*)  d_in[1];
    const float* Wp    = (const float*)d_in[2];
    const float* bp    = (const float*)d_in[3];
    const float* Wq    = (const float*)d_in[4];
    const float* bq    = (const float*)d_in[5];
    const float* Wk    = (const float*)d_in[6];
    const float* bk    = (const float*)d_in[7];
    const float* Wv    = (const float*)d_in[8];
    const float* bv    = (const float*)d_in[9];
    const float* Eemb  = (const float*)d_in[10];
    const float* Wr1   = (const float*)d_in[11];
    const float* br1   = (const float*)d_in[12];
    const float* Wr2   = (const float*)d_in[13];
    const float* Wf1   = (const float*)d_in[14];
    const float* bf1   = (const float*)d_in[15];
    const float* Wf2   = (const float*)d_in[16];
    const float* bf2   = (const float*)d_in[17];
    const float* ln_g  = (const float*)d_in[18];
    const float* ln_b  = (const float*)d_in[19];
    const float* Ws1   = (const float*)d_in[20];
    const float* bs1   = (const float*)d_in[21];
    const float* Ws2   = (const float*)d_in[22];
    const float* bs2   = (const float*)d_in[23];
    float* out = (float*)d_out;

    cudaFuncSetAttribute(attn_kernel, cudaFuncAttributeMaxDynamicSharedMemorySize, SMEM_BYTES);

    qkv_kernel<<<BB*NN/64, 256>>>(x, Wp, bp, Wq, bq, Wk, bk, Wv, bv,
                                  Eemb, Wr1, br1, Wr2);
    dim3 grid(NN/64, BB);
    attn_kernel<<<grid, 512, SMEM_BYTES>>>(ranks, Wf1, bf1, Wf2, bf2,
                                           ln_g, ln_b, Ws1, bs1, Ws2, bs2, out);
}

// round 3
// speedup vs baseline: 1.4560x; 1.1048x over previous
#include <cuda_runtime.h>

#define BB   16
#define NN   512
#define DIN  256
#define DD   64
#define EE   32
#define MAXDIST 50

typedef unsigned long long ull;

// -------- packed f32x2 helpers --------
__device__ __forceinline__ void fma2(ull& d, ull a, ull b) {
    asm("fma.rn.f32x2 %0, %1, %2, %0;" : "+l"(d) : "l"(a), "l"(b));
}
__device__ __forceinline__ ull dup2(float x) {
    unsigned u = __float_as_uint(x); ull d;
    asm("mov.b64 %0, {%1, %1};" : "=l"(d) : "r"(u));
    return d;
}
__device__ __forceinline__ float2 unpk(ull u) {
    unsigned lo, hi;
    asm("mov.b64 {%0, %1}, %2;" : "=r"(lo), "=r"(hi) : "l"(u));
    return make_float2(__uint_as_float(lo), __uint_as_float(hi));
}

// -------- scratch --------
__device__ float g_qT[BB*DD*NN];   // per batch: [d][n]
__device__ float g_kT[BB*DD*NN];   // per batch: [d][n]
__device__ float g_v [BB*NN*DD];   // row-major [n][d]
__device__ float g_rel[MAXDIST+1];

// ============================================================
// Kernel 1: xp = x@Wp+bp ; q,k,v = xp@W{q,k,v}+b (fused, FFMA2)
// ============================================================
__global__ __launch_bounds__(256) void qkv_kernel(
    const float* __restrict__ x,
    const float* __restrict__ Wp, const float* __restrict__ bp,
    const float* __restrict__ Wq, const float* __restrict__ bq,
    const float* __restrict__ Wk, const float* __restrict__ bk,
    const float* __restrict__ Wv, const float* __restrict__ bv,
    const float* __restrict__ Eemb, const float* __restrict__ Wr1,
    const float* __restrict__ br1,  const float* __restrict__ Wr2) {
    __shared__ float bufA[64*68];
    __shared__ float bufB[64*68];
    const int tid = threadIdx.x;
    const int ty = tid >> 4, tx = tid & 15;
    const int row0 = blockIdx.x * 64;
    const int b = row0 >> 9;
    const int n0 = row0 & 511;

    if (blockIdx.x == 0 && tid <= MAXDIST) {
        float e[EE];
#pragma unroll
        for (int c = 0; c < EE; c++) e[c] = Eemb[tid*EE + c];
        float w = 0.f;
#pragma unroll
        for (int j = 0; j < 16; j++) {
            float h = br1[j];
#pragma unroll
            for (int c = 0; c < EE; c++) h = fmaf(e[c], Wr1[c*16 + j], h);
            h = fmaxf(h, 0.f);
            w = fmaf(h, Wr2[j], w);
        }
        g_rel[tid] = 1.f / (1.f + __expf(-w));
    }

    // --- xp = x @ Wp ---
    float ra[16], rb[16];
#pragma unroll
    for (int j = 0; j < 16; j++) {
        int idx = tid + j*256;
        ra[j] = x[(row0 + (idx >> 6))*DIN + (idx & 63)];
        rb[j] = Wp[(idx >> 6)*DD + (idx & 63)];
    }
    ull acc2[2][4];
#pragma unroll
    for (int p = 0; p < 2; p++)
#pragma unroll
        for (int c = 0; c < 4; c++) acc2[p][c] = 0ULL;

    for (int kc = 0; kc < 4; kc++) {
#pragma unroll
        for (int j = 0; j < 16; j++) {
            int idx = tid + j*256;
            bufA[(idx & 63)*68 + (idx >> 6)] = ra[j];
            bufB[(idx >> 6)*68 + (idx & 63)] = rb[j];
        }
        __syncthreads();
        if (kc < 3) {
#pragma unroll
            for (int j = 0; j < 16; j++) {
                int idx = tid + j*256;
                ra[j] = x[(row0 + (idx >> 6))*DIN + (kc+1)*64 + (idx & 63)];
                rb[j] = Wp[((kc+1)*64 + (idx >> 6))*DD + (idx & 63)];
            }
        }
#pragma unroll 8
        for (int kk = 0; kk < 64; kk++) {
            ulonglong2 a = *(const ulonglong2*)&bufA[kk*68 + ty*4];
            float4 bw = *(const float4*)&bufB[kk*68 + tx*4];
            ull b0 = dup2(bw.x), b1 = dup2(bw.y), b2 = dup2(bw.z), b3 = dup2(bw.w);
            fma2(acc2[0][0], a.x, b0); fma2(acc2[0][1], a.x, b1);
            fma2(acc2[0][2], a.x, b2); fma2(acc2[0][3], a.x, b3);
            fma2(acc2[1][0], a.y, b0); fma2(acc2[1][1], a.y, b1);
            fma2(acc2[1][2], a.y, b2); fma2(acc2[1][3], a.y, b3);
        }
        __syncthreads();
    }
    // xpT into bufA (float4 along rows)
#pragma unroll
    for (int c = 0; c < 4; c++) {
        float2 p0 = unpk(acc2[0][c]), p1 = unpk(acc2[1][c]);
        float bias = bp[tx*4 + c];
        float4 v4 = {p0.x + bias, p0.y + bias, p1.x + bias, p1.y + bias};
        *(float4*)&bufA[(tx*4 + c)*68 + ty*4] = v4;
    }
    __syncthreads();

    const float* Ws[3] = {Wq, Wk, Wv};
    const float* bs[3] = {bq, bk, bv};
    for (int t = 0; t < 3; t++) {
#pragma unroll
        for (int j = 0; j < 16; j++) {
            int idx = tid + j*256;
            bufB[(idx >> 6)*68 + (idx & 63)] = Ws[t][idx];
        }
        __syncthreads();
        ull o2[2][4];
#pragma unroll
        for (int p = 0; p < 2; p++)
#pragma unroll
            for (int c = 0; c < 4; c++) o2[p][c] = 0ULL;
#pragma unroll 8
        for (int kk = 0; kk < 64; kk++) {
            ulonglong2 a = *(const ulonglong2*)&bufA[kk*68 + ty*4];
            float4 bw = *(const float4*)&bufB[kk*68 + tx*4];
            ull b0 = dup2(bw.x), b1 = dup2(bw.y), b2 = dup2(bw.z), b3 = dup2(bw.w);
            fma2(o2[0][0], a.x, b0); fma2(o2[0][1], a.x, b1);
            fma2(o2[0][2], a.x, b2); fma2(o2[0][3], a.x, b3);
            fma2(o2[1][0], a.y, b0); fma2(o2[1][1], a.y, b1);
            fma2(o2[1][2], a.y, b2); fma2(o2[1][3], a.y, b3);
        }
        if (t == 2) {
            // v row-major: per row r, float4 of cols
            float2 u[2][4];
#pragma unroll
            for (int p = 0; p < 2; p++)
#pragma unroll
                for (int c = 0; c < 4; c++) u[p][c] = unpk(o2[p][c]);
            float4 bias = *(const float4*)&bs[2][tx*4];
#pragma unroll
            for (int r = 0; r < 4; r++) {
                float4 v4;
                float2* up = u[r >> 1];
                if (r & 1) v4 = make_float4(up[0].y + bias.x, up[1].y + bias.y, up[2].y + bias.z, up[3].y + bias.w);
                else       v4 = make_float4(up[0].x + bias.x, up[1].x + bias.y, up[2].x + bias.z, up[3].x + bias.w);
                *(float4*)&g_v[(row0 + ty*4 + r)*DD + tx*4] = v4;
            }
        } else {
            // q, k transposed: STG.128 along n per column
            float* dst = (t == 0) ? g_qT : g_kT;
#pragma unroll
            for (int c = 0; c < 4; c++) {
                float2 p0 = unpk(o2[0][c]), p1 = unpk(o2[1][c]);
                float bias = bs[t][tx*4 + c];
                float4 v4 = {p0.x + bias, p0.y + bias, p1.x + bias, p1.y + bias};
                *(float4*)&dst[b*DD*NN + (tx*4 + c)*NN + n0 + ty*4] = v4;
            }
        }
        __syncthreads();
    }
}

// ============================================================
// Kernel 2: fused attention + FFN + LN + head. 512 threads, FFMA2.
// ============================================================
#define S_STRIDE 516
#define R1_OFF   33024
#define R2_OFF   49664
#define REL_OFF  54016
#define RK_OFF   54080
#define SMEM_FLOATS 54592
#define SMEM_BYTES  (SMEM_FLOATS*4)

__global__ __launch_bounds__(512) void attn_kernel(
    const int* __restrict__ ranks,
    const float* __restrict__ Wf1, const float* __restrict__ bf1,
    const float* __restrict__ Wf2, const float* __restrict__ bf2,
    const float* __restrict__ ln_g, const float* __restrict__ ln_b,
    const float* __restrict__ Ws1, const float* __restrict__ bs1,
    const float* __restrict__ Ws2, const float* __restrict__ bs2,
    float* __restrict__ out) {
    extern __shared__ float sm[];
    float* S   = sm;
    float* R1  = sm + R1_OFF;
    float* R2  = sm + R2_OFF;
    float* rel = sm + REL_OFF;
    int*   rk  = (int*)(sm + RK_OFF);

    const int tid = threadIdx.x;
    const int b = blockIdx.y;
    const int q0 = blockIdx.x * 64;
    const int base = b * NN;
    const int bT = b * DD * NN;

    if (tid <= MAXDIST) rel[tid] = g_rel[tid];
    for (int m = tid; m < NN; m += 512) rk[m] = ranks[base + m];
#pragma unroll
    for (int j = 0; j < 8; j++) {
        int idx = tid + j*512;
        int d = idx >> 6, i = idx & 63;
        R2[d*68 + i] = g_qT[bT + d*NN + q0 + i];
    }
    __syncthreads();

    // ---- Phase 1: S = (QK^T/8)*rel. 8 rows x 4 keys per thread, FFMA2 ----
    {
        const int ty = tid >> 6;        // 0..7 (8 rows each)
        const int tx = tid & 63;        // 4 keys each
        int ri[8];
#pragma unroll
        for (int rr = 0; rr < 8; rr++) ri[rr] = rk[q0 + ty*8 + rr];

        for (int kc = 0; kc < 2; kc++) {
            const int k0 = kc * 256;
#pragma unroll
            for (int j = 0; j < 32; j++) {
                int idx = tid + j*512;
                int d = idx >> 8, key = idx & 255;
                R1[d*260 + key] = g_kT[bT + d*NN + k0 + key];
            }
            __syncthreads();
            ull acc2[4][4];
#pragma unroll
            for (int p = 0; p < 4; p++)
#pragma unroll
                for (int c = 0; c < 4; c++) acc2[p][c] = 0ULL;
#pragma unroll 4
            for (int d = 0; d < 64; d++) {
                ulonglong2 a01 = *(const ulonglong2*)&R2[d*68 + ty*8];
                ulonglong2 a23 = *(const ulonglong2*)&R2[d*68 + ty*8 + 4];
                float4 kb = *(const float4*)&R1[d*260 + tx*4];
                ull b0 = dup2(kb.x), b1 = dup2(kb.y), b2 = dup2(kb.z), b3 = dup2(kb.w);
                fma2(acc2[0][0], a01.x, b0); fma2(acc2[0][1], a01.x, b1);
                fma2(acc2[0][2], a01.x, b2); fma2(acc2[0][3], a01.x, b3);
                fma2(acc2[1][0], a01.y, b0); fma2(acc2[1][1], a01.y, b1);
                fma2(acc2[1][2], a01.y, b2); fma2(acc2[1][3], a01.y, b3);
                fma2(acc2[2][0], a23.x, b0); fma2(acc2[2][1], a23.x, b1);
                fma2(acc2[2][2], a23.x, b2); fma2(acc2[2][3], a23.x, b3);
                fma2(acc2[3][0], a23.y, b0); fma2(acc2[3][1], a23.y, b1);
                fma2(acc2[3][2], a23.y, b2); fma2(acc2[3][3], a23.y, b3);
            }
            int rkc[4];
#pragma unroll
            for (int c = 0; c < 4; c++) rkc[c] = rk[k0 + tx*4 + c];
#pragma unroll
            for (int p = 0; p < 4; p++) {
                float4 olo, ohi;
                float* plo = (float*)&olo;
                float* phi = (float*)&ohi;
                int rlo = ri[2*p], rhi = ri[2*p + 1];
#pragma unroll
                for (int c = 0; c < 4; c++) {
                    float2 u = unpk(acc2[p][c]);
                    int d0 = rlo - rkc[c]; if (d0 < 0) d0 = -d0; if (d0 > MAXDIST) d0 = MAXDIST;
                    int d1 = rhi - rkc[c]; if (d1 < 0) d1 = -d1; if (d1 > MAXDIST) d1 = MAXDIST;
                    plo[c] = u.x * 0.125f * rel[d0];
                    phi[c] = u.y * 0.125f * rel[d1];
                }
                *(float4*)&S[(ty*8 + 2*p    )*S_STRIDE + k0 + tx*4] = olo;
                *(float4*)&S[(ty*8 + 2*p + 1)*S_STRIDE + k0 + tx*4] = ohi;
            }
            __syncthreads();
        }
    }

    // ---- Phase 2: row softmax ----
    {
        const int warp = tid >> 5, lane = tid & 31;
#pragma unroll
        for (int rr = 0; rr < 4; rr++) {
            float* Sr = S + (warp*4 + rr)*S_STRIDE;
            float mx = -1e30f;
#pragma unroll
            for (int j = 0; j < 16; j++) mx = fmaxf(mx, Sr[lane + j*32]);
#pragma unroll
            for (int o = 16; o >= 1; o >>= 1) mx = fmaxf(mx, __shfl_xor_sync(0xffffffffu, mx, o));
            float sum = 0.f;
#pragma unroll
            for (int j = 0; j < 16; j++) {
                float e = __expf(Sr[lane + j*32] - mx);
                Sr[lane + j*32] = e; sum += e;
            }
#pragma unroll
            for (int o = 16; o >= 1; o >>= 1) sum += __shfl_xor_sync(0xffffffffu, sum, o);
            float inv = 1.f / sum;
#pragma unroll
            for (int j = 0; j < 16; j++) Sr[lane + j*32] *= inv;
        }
    }
    __syncthreads();

    // ---- Phase 3: AO = P@V, split-K 4 groups x 128 threads, FFMA2 ----
    {
        const int g3   = tid >> 7;      // 0..3
        const int t3   = tid & 127;
        const int rowg = t3 >> 3;       // 0..15 -> rows rowg*4..+3
        const int colg = t3 & 7;        // cols colg*8..+7
        ull acc2[4][4];                 // [row][colpair]
#pragma unroll
        for (int r = 0; r < 4; r++)
#pragma unroll
            for (int c = 0; c < 4; c++) acc2[r][c] = 0ULL;

        for (int rnd = 0; rnd < 2; rnd++) {
#pragma unroll
            for (int j = 0; j < 32; j++) {
                int idx = tid + j*512;
                int key = idx >> 6, d = idx & 63;
                R1[key*64 + d] = g_v[(base + rnd*256 + key)*DD + d];
            }
            __syncthreads();
            const int kl0 = g3 * 64;
            const int kg0 = rnd*256 + kl0;
#pragma unroll 4
            for (int kl = 0; kl < 64; kl++) {
                int key = kg0 + kl;
                ull pa0 = dup2(S[(rowg*4 + 0)*S_STRIDE + key]);
                ull pa1 = dup2(S[(rowg*4 + 1)*S_STRIDE + key]);
                ull pa2 = dup2(S[(rowg*4 + 2)*S_STRIDE + key]);
                ull pa3 = dup2(S[(rowg*4 + 3)*S_STRIDE + key]);
                ulonglong2 v0 = *(const ulonglong2*)&R1[(kl0 + kl)*64 + colg*8];
                ulonglong2 v1 = *(const ulonglong2*)&R1[(kl0 + kl)*64 + colg*8 + 4];
                fma2(acc2[0][0], pa0, v0.x); fma2(acc2[0][1], pa0, v0.y);
                fma2(acc2[0][2], pa0, v1.x); fma2(acc2[0][3], pa0, v1.y);
                fma2(acc2[1][0], pa1, v0.x); fma2(acc2[1][1], pa1, v0.y);
                fma2(acc2[1][2], pa1, v1.x); fma2(acc2[1][3], pa1, v1.y);
                fma2(acc2[2][0], pa2, v0.x); fma2(acc2[2][1], pa2, v0.y);
                fma2(acc2[2][2], pa2, v1.x); fma2(acc2[2][3], pa2, v1.y);
                fma2(acc2[3][0], pa3, v0.x); fma2(acc2[3][1], pa3, v0.y);
                fma2(acc2[3][2], pa3, v1.x); fma2(acc2[3][3], pa3, v1.y);
            }
            __syncthreads();
        }
        // unpack
        float po[4][8];
#pragma unroll
        for (int r = 0; r < 4; r++)
#pragma unroll
            for (int c = 0; c < 4; c++) {
                float2 u = unpk(acc2[r][c]);
                po[r][2*c] = u.x; po[r][2*c + 1] = u.y;
            }
        // groups 1..3 write partials into S (dead now)
        if (g3 > 0) {
            float* part = S + (g3 - 1)*4096;
#pragma unroll
            for (int r = 0; r < 4; r++) {
                *(float4*)&part[(rowg*4 + r)*64 + colg*8]     = *(float4*)&po[r][0];
                *(float4*)&part[(rowg*4 + r)*64 + colg*8 + 4] = *(float4*)&po[r][4];
            }
        }
        __syncthreads();
        if (g3 == 0) {
#pragma unroll
            for (int gg = 0; gg < 3; gg++) {
                float* part = S + gg*4096;
#pragma unroll
                for (int r = 0; r < 4; r++) {
                    float4 p0 = *(const float4*)&part[(rowg*4 + r)*64 + colg*8];
                    float4 p1 = *(const float4*)&part[(rowg*4 + r)*64 + colg*8 + 4];
                    po[r][0] += p0.x; po[r][1] += p0.y; po[r][2] += p0.z; po[r][3] += p0.w;
                    po[r][4] += p1.x; po[r][5] += p1.y; po[r][6] += p1.z; po[r][7] += p1.w;
                }
            }
            // aoT [d][row] stride 68 into R1, float4 along rows
#pragma unroll
            for (int c = 0; c < 8; c++) {
                float4 v4 = {po[0][c], po[1][c], po[2][c], po[3][c]};
                *(float4*)&R1[(colg*8 + c)*68 + rowg*4] = v4;
            }
        } else {
            // groups 1..3 stage w1 = Wf1 into R1+4352
            float* w1 = R1 + 4352;
            for (int j = (g3 - 1)*128 + t3; j < 8192; j += 384) w1[j] = Wf1[j];
        }
    }
    __syncthreads();

    // ---- Phase 4a: h1 = relu(ao@Wf1+bf1)  (64x128), FFMA2 ----
    {
        const float* w1 = R1 + 4352;
        const int ty = tid >> 5, tx = tid & 31;     // rows ty*4, cols tx*4
        ull acc2[2][4];
#pragma unroll
        for (int p = 0; p < 2; p++)
#pragma unroll
            for (int c = 0; c < 4; c++) acc2[p][c] = 0ULL;
#pragma unroll 4
        for (int kk = 0; kk < 64; kk++) {
            ulonglong2 a = *(const ulonglong2*)&R1[kk*68 + ty*4];
            float4 bw = *(const float4*)&w1[kk*128 + tx*4];
            ull b0 = dup2(bw.x), b1 = dup2(bw.y), b2 = dup2(bw.z), b3 = dup2(bw.w);
            fma2(acc2[0][0], a.x, b0); fma2(acc2[0][1], a.x, b1);
            fma2(acc2[0][2], a.x, b2); fma2(acc2[0][3], a.x, b3);
            fma2(acc2[1][0], a.y, b0); fma2(acc2[1][1], a.y, b1);
            fma2(acc2[1][2], a.y, b2); fma2(acc2[1][3], a.y, b3);
        }
        __syncthreads();   // R1 reads done before w2 overwrite; S writes safe
        // relu+bias, h1T into S (stride 68)
#pragma unroll
        for (int c = 0; c < 4; c++) {
            float bias = bf1[tx*4 + c];
            float2 u0 = unpk(acc2[0][c]), u1 = unpk(acc2[1][c]);
            float4 v4 = {fmaxf(u0.x + bias, 0.f), fmaxf(u0.y + bias, 0.f),
                         fmaxf(u1.x + bias, 0.f), fmaxf(u1.y + bias, 0.f)};
            *(float4*)&S[(tx*4 + c)*68 + ty*4] = v4;
        }
#pragma unroll
        for (int j = 0; j < 16; j++) R1[tid + j*512] = Wf2[tid + j*512];
    }
    __syncthreads();

    // ---- Phase 4b: h2 = h1@Wf2+bf2, LayerNorm, FFMA2 ----
    {
        const int ty = tid >> 5, tx = tid & 31;     // rows ty*4, cols tx*2
        ull acc2[2][2];
        acc2[0][0] = acc2[0][1] = acc2[1][0] = acc2[1][1] = 0ULL;
#pragma unroll 4
        for (int kk = 0; kk < 128; kk++) {
            ulonglong2 a = *(const ulonglong2*)&S[kk*68 + ty*4];
            float2 bw = *(const float2*)&R1[kk*64 + tx*2];
            ull b0 = dup2(bw.x), b1 = dup2(bw.y);
            fma2(acc2[0][0], a.x, b0); fma2(acc2[0][1], a.x, b1);
            fma2(acc2[1][0], a.y, b0); fma2(acc2[1][1], a.y, b1);
        }
        __syncthreads();   // R1 reads done before ws1 staging
        float h2[4][2];
        {
            float2 u00 = unpk(acc2[0][0]), u01 = unpk(acc2[0][1]);
            float2 u10 = unpk(acc2[1][0]), u11 = unpk(acc2[1][1]);
            h2[0][0] = u00.x; h2[0][1] = u01.x;
            h2[1][0] = u00.y; h2[1][1] = u01.y;
            h2[2][0] = u10.x; h2[2][1] = u11.x;
            h2[3][0] = u10.y; h2[3][1] = u11.y;
        }
        float b0 = bf2[tx*2], b1 = bf2[tx*2 + 1];
        float g0v = ln_g[tx*2], g1v = ln_g[tx*2 + 1];
        float be0 = ln_b[tx*2], be1 = ln_b[tx*2 + 1];
#pragma unroll
        for (int r = 0; r < 4; r++) {
            float e0 = h2[r][0] + b0, e1 = h2[r][1] + b1;
            float s  = e0 + e1;
            float s2 = e0*e0 + e1*e1;
#pragma unroll
            for (int o = 16; o >= 1; o >>= 1) {
                s  += __shfl_xor_sync(0xffffffffu, s,  o);
                s2 += __shfl_xor_sync(0xffffffffu, s2, o);
            }
            float mu = s * (1.f/64.f);
            float var = s2 * (1.f/64.f) - mu*mu;
            float inv = rsqrtf(var + 1e-5f);
            R2[(tx*2 + 0)*68 + ty*4 + r] = (e0 - mu)*inv*g0v + be0;   // hnT
            R2[(tx*2 + 1)*68 + ty*4 + r] = (e1 - mu)*inv*g1v + be1;
        }
    }
    {
        for (int j = tid; j < 2048; j += 512) R1[j] = Ws1[j];
        if (tid < 32) R1[2048 + tid] = Ws2[tid];
    }
    __syncthreads();

    // ---- Phase 4c: head (threads 0..255) ----
    if (tid < 256) {
        const int ty = tid >> 4, tx = tid & 15;
        float s1[4][2];
#pragma unroll
        for (int r = 0; r < 4; r++) { s1[r][0] = 0.f; s1[r][1] = 0.f; }
#pragma unroll 4
        for (int kk = 0; kk < 64; kk++) {
            float4 a = *(const float4*)&R2[kk*68 + ty*4];
            float w0 = R1[kk*32 + tx*2], w1b = R1[kk*32 + tx*2 + 1];
            s1[0][0] = fmaf(a.x, w0, s1[0][0]); s1[0][1] = fmaf(a.x, w1b, s1[0][1]);
            s1[1][0] = fmaf(a.y, w0, s1[1][0]); s1[1][1] = fmaf(a.y, w1b, s1[1][1]);
            s1[2][0] = fmaf(a.z, w0, s1[2][0]); s1[2][1] = fmaf(a.z, w1b, s1[2][1]);
            s1[3][0] = fmaf(a.w, w0, s1[3][0]); s1[3][1] = fmaf(a.w, w1b, s1[3][1]);
        }
        float w2a = R1[2048 + tx*2], w2b = R1[2048 + tx*2 + 1];
        float ba = bs1[tx*2], bb = bs1[tx*2 + 1];
        float bs2v = bs2[0];
#pragma unroll
        for (int r = 0; r < 4; r++) {
            float pa = fmaxf(s1[r][0] + ba, 0.f);
            float pb = fmaxf(s1[r][1] + bb, 0.f);
            float p = pa*w2a + pb*w2b;
#pragma unroll
            for (int o = 8; o >= 1; o >>= 1) p += __shfl_xor_sync(0xffffffffu, p, o, 16);
            if (tx == 0) {
                float z = p + bs2v;
                out[base + q0 + ty*4 + r] = 1.f / (1.f + __expf(-z));
            }
        }
    }
}

// ============================================================
extern "C" void kernel_launch(void* const* d_in, const int* in_sizes, int n_in,
                              void* d_out, int out_size) {
    const float* x     = (const float*)d_in[0];
    const int*   ranks = (const int*)  d_in[1];
    const float* Wp    = (const float*)d_in[2];
    const float* bp    = (const float*)d_in[3];
    const float* Wq    = (const float*)d_in[4];
    const float* bq    = (const float*)d_in[5];
    const float* Wk    = (const float*)d_in[6];
    const float* bk    = (const float*)d_in[7];
    const float* Wv    = (const float*)d_in[8];
    const float* bv    = (const float*)d_in[9];
    const float* Eemb  = (const float*)d_in[10];
    const float* Wr1   = (const float*)d_in[11];
    const float* br1   = (const float*)d_in[12];
    const float* Wr2   = (const float*)d_in[13];
    const float* Wf1   = (const float*)d_in[14];
    const float* bf1   = (const float*)d_in[15];
    const float* Wf2   = (const float*)d_in[16];
    const float* bf2   = (const float*)d_in[17];
    const float* ln_g  = (const float*)d_in[18];
    const float* ln_b  = (const float*)d_in[19];
    const float* Ws1   = (const float*)d_in[20];
    const float* bs1   = (const float*)d_in[21];
    const float* Ws2   = (const float*)d_in[22];
    const float* bs2   = (const float*)d_in[23];
    float* out = (float*)d_out;

    cudaFuncSetAttribute(attn_kernel, cudaFuncAttributeMaxDynamicSharedMemorySize, SMEM_BYTES);

    qkv_kernel<<<BB*NN/64, 256>>>(x, Wp, bp, Wq, bq, Wk, bk, Wv, bv,
                                  Eemb, Wr1, br1, Wr2);
    dim3 grid(NN/64, BB);
    attn_kernel<<<grid, 512, SMEM_BYTES>>>(ranks, Wf1, bf1, Wf2, bf2,
                                           ln_g, ln_b, Ws1, bs1, Ws2, bs2, out);
}